// round 2
// baseline (speedup 1.0000x reference)
#include <cuda_runtime.h>
#include <cstdint>
#include <math.h>

// Problem constants
#define BB 64
#define TT 2048
#define II 64
#define HH 128

// ---------- packed f32x2 / fast-math helpers ----------
__device__ __forceinline__ unsigned long long ffma2(unsigned long long a,
                                                    unsigned long long b,
                                                    unsigned long long c) {
    unsigned long long d;
    asm("fma.rn.f32x2 %0, %1, %2, %3;" : "=l"(d) : "l"(a), "l"(b), "l"(c));
    return d;
}
__device__ __forceinline__ unsigned long long fadd2(unsigned long long a,
                                                    unsigned long long b) {
    unsigned long long d;
    asm("add.rn.f32x2 %0, %1, %2;" : "=l"(d) : "l"(a), "l"(b));
    return d;
}
__device__ __forceinline__ float2 unpack2(unsigned long long v) {
    float2 f;
    asm("mov.b64 {%0, %1}, %2;" : "=f"(f.x), "=f"(f.y) : "l"(v));
    return f;
}
__device__ __forceinline__ float tanh_fast(float x) {
    float y;
    asm("tanh.approx.f32 %0, %1;" : "=f"(y) : "f"(x));
    return y;
}

// ============================================================================
// Phase 1: xw[b,t,i] = dot(x[b,t,:], W[i,:]) + b_ih[i] + b_hh[i]
// Written directly into the output region of d_out (overwritten in-place by
// the scan kernel later). One block = 64 (b,t) rows, 128 threads (one per i).
// ============================================================================
__global__ __launch_bounds__(128) void xw_gemm_kernel(
    const float* __restrict__ x,
    const float* __restrict__ W,
    const float* __restrict__ b_ih,
    const float* __restrict__ b_hh,
    float* __restrict__ out)
{
    const int ROWS = 64;
    const int i = threadIdx.x;
    const long long row0 = (long long)blockIdx.x * ROWS;

    unsigned long long w[32];
    const ulonglong2* Wrow = (const ulonglong2*)(W + i * II);
#pragma unroll
    for (int k = 0; k < 16; k++) {
        ulonglong2 t = Wrow[k];
        w[2 * k]     = t.x;
        w[2 * k + 1] = t.y;
    }
    const float bias = b_ih[i] + b_hh[i];

    __shared__ __align__(16) float xs[2][II];

    const float4* xg = (const float4*)(x + row0 * II);

    float4 pre = make_float4(0.f, 0.f, 0.f, 0.f);
    if (i < 16) {
        ((float4*)xs[0])[i] = xg[i];
        pre = xg[16 + i];
    }
    __syncthreads();

    for (int r = 0; r < ROWS; r++) {
        float4 nxt = make_float4(0.f, 0.f, 0.f, 0.f);
        if (i < 16) {
            int rr = (r + 2 < ROWS) ? (r + 2) : r;
            nxt = xg[rr * 16 + i];
        }

        const ulonglong2* hv = (const ulonglong2*)xs[r & 1];
        unsigned long long a0 = 0ull, a1 = 0ull, a2 = 0ull, a3 = 0ull;
#pragma unroll
        for (int k = 0; k < 16; k += 2) {
            ulonglong2 hA = hv[k];
            ulonglong2 hB = hv[k + 1];
            a0 = ffma2(w[2 * k],     hA.x, a0);
            a1 = ffma2(w[2 * k + 1], hA.y, a1);
            a2 = ffma2(w[2 * k + 2], hB.x, a2);
            a3 = ffma2(w[2 * k + 3], hB.y, a3);
        }
        unsigned long long s = fadd2(fadd2(a0, a1), fadd2(a2, a3));
        float2 f = unpack2(s);
        out[(row0 + r) * HH + i] = f.x + f.y + bias;

        if (i < 16) ((float4*)xs[(r + 1) & 1])[i] = pre;
        __syncthreads();
        pre = nxt;
    }
}

// ============================================================================
// Phase 2: sequential scan.  256 threads/block = TWO independent batch
// elements (group g = tid>>7).  Each group of 128 threads runs its own
// recurrence synchronized by a NAMED barrier (bar.sync g+1, 128) so the two
// groups never couple.  2 warps per SMSP -> latency hiding.
// Thread i holds U row i in 64 packed f32x2 regs; 8 accumulator chains
// (depth 8) reduced with packed adds; hardware tanh.approx.
// ============================================================================
__global__ __launch_bounds__(256, 1) void rnn_scan_kernel(
    const float* __restrict__ h0,
    const float* __restrict__ U,
    float* __restrict__ out)
{
    const int tid = threadIdx.x;
    const int g   = tid >> 7;          // 0 or 1
    const int i   = tid & 127;
    const int b   = blockIdx.x * 2 + g;

    __shared__ __align__(16) float h_s[2][2][HH];   // [group][buf][i]

    // Load U row i (128 floats) into 64 packed regs
    unsigned long long u[64];
    const ulonglong2* Urow = (const ulonglong2*)(U + i * HH);
#pragma unroll
    for (int k = 0; k < 32; k++) {
        ulonglong2 t = Urow[k];
        u[2 * k]     = t.x;
        u[2 * k + 1] = t.y;
    }

    h_s[g][0][i] = h0[b * HH + i];

    float* op = out + (size_t)b * TT * HH + i;

    // prefetch distance 2 on xw (phase-1 data, in-place)
    float xw0 = op[0];
    float xw1 = op[HH];
    __syncthreads();   // one full-block sync to cover initial smem writes

    int buf = 0;
    float v = 0.f;
#pragma unroll 1
    for (int t = 0; t < TT; t++) {
        int tp = (t + 2 < TT) ? (t + 2) : t;
        float xw2 = op[tp * HH];

        const ulonglong2* hv = (const ulonglong2*)h_s[g][buf];
        unsigned long long acc[8];
#pragma unroll
        for (int j = 0; j < 8; j++) acc[j] = 0ull;
#pragma unroll
        for (int k = 0; k < 32; k++) {
            ulonglong2 hA = hv[k];
            acc[(2 * k)     & 7] = ffma2(u[2 * k],     hA.x, acc[(2 * k)     & 7]);
            acc[(2 * k + 1) & 7] = ffma2(u[2 * k + 1], hA.y, acc[(2 * k + 1) & 7]);
        }
        // tree reduce: 8 -> 4 -> 2 -> 1 packed, then unpack
        unsigned long long s0 = fadd2(acc[0], acc[4]);
        unsigned long long s1 = fadd2(acc[1], acc[5]);
        unsigned long long s2 = fadd2(acc[2], acc[6]);
        unsigned long long s3 = fadd2(acc[3], acc[7]);
        unsigned long long s  = fadd2(fadd2(s0, s1), fadd2(s2, s3));
        float2 f = unpack2(s);
        float dot = f.x + f.y;

        v = tanh_fast(xw0 + dot);

        op[t * HH] = v;              // output h_t (overwrites xw[t])
        h_s[g][buf ^ 1][i] = v;      // publish new state
        // named barrier: only this group's 128 threads
        asm volatile("bar.sync %0, %1;" :: "r"(g + 1), "r"(128) : "memory");

        xw0 = xw1;
        xw1 = xw2;
        buf ^= 1;
    }

    // h_last: thread i's final value is v from the last step
    out[(size_t)BB * TT * HH + b * HH + i] = v;
}

// ============================================================================
// Launch
// ============================================================================
extern "C" void kernel_launch(void* const* d_in, const int* in_sizes, int n_in,
                              void* d_out, int out_size)
{
    (void)in_sizes; (void)n_in; (void)out_size;
    const float* x    = (const float*)d_in[0];
    const float* h0   = (const float*)d_in[1];
    const float* W    = (const float*)d_in[2];
    const float* U    = (const float*)d_in[3];
    const float* b_ih = (const float*)d_in[4];
    const float* b_hh = (const float*)d_in[5];
    float* out = (float*)d_out;

    xw_gemm_kernel<<<(BB * TT) / 64, 128>>>(x, W, b_ih, b_hh, out);
    rnn_scan_kernel<<<BB / 2, 256>>>(h0, U, out);
}

// round 3
// speedup vs baseline: 1.1197x; 1.1197x over previous
#include <cuda_runtime.h>
#include <cstdint>
#include <math.h>

// Problem constants
#define BB 64
#define TT 2048
#define II 64
#define HH 128

// ---------- packed f32x2 / fast-math helpers ----------
__device__ __forceinline__ unsigned long long ffma2(unsigned long long a,
                                                    unsigned long long b,
                                                    unsigned long long c) {
    unsigned long long d;
    asm("fma.rn.f32x2 %0, %1, %2, %3;" : "=l"(d) : "l"(a), "l"(b), "l"(c));
    return d;
}
__device__ __forceinline__ unsigned long long fadd2(unsigned long long a,
                                                    unsigned long long b) {
    unsigned long long d;
    asm("add.rn.f32x2 %0, %1, %2;" : "=l"(d) : "l"(a), "l"(b));
    return d;
}
__device__ __forceinline__ float2 unpack2(unsigned long long v) {
    float2 f;
    asm("mov.b64 {%0, %1}, %2;" : "=f"(f.x), "=f"(f.y) : "l"(v));
    return f;
}
__device__ __forceinline__ float tanh_fast(float x) {
    float y;
    asm("tanh.approx.f32 %0, %1;" : "=f"(y) : "f"(x));
    return y;
}

// ============================================================================
// Phase 1: xw[b,t,i] = dot(x[b,t,:], W[i,:]) + b_ih[i] + b_hh[i]
// Written directly into the output region of d_out (overwritten in-place by
// the scan kernel later). One block = 64 (b,t) rows, 128 threads.
// ============================================================================
__global__ __launch_bounds__(128) void xw_gemm_kernel(
    const float* __restrict__ x,
    const float* __restrict__ W,
    const float* __restrict__ b_ih,
    const float* __restrict__ b_hh,
    float* __restrict__ out)
{
    const int ROWS = 64;
    const int i = threadIdx.x;
    const long long row0 = (long long)blockIdx.x * ROWS;

    unsigned long long w[32];
    const ulonglong2* Wrow = (const ulonglong2*)(W + i * II);
#pragma unroll
    for (int k = 0; k < 16; k++) {
        ulonglong2 t = Wrow[k];
        w[2 * k]     = t.x;
        w[2 * k + 1] = t.y;
    }
    const float bias = b_ih[i] + b_hh[i];

    __shared__ __align__(16) float xs[2][II];

    const float4* xg = (const float4*)(x + row0 * II);

    float4 pre = make_float4(0.f, 0.f, 0.f, 0.f);
    if (i < 16) {
        ((float4*)xs[0])[i] = xg[i];
        pre = xg[16 + i];
    }
    __syncthreads();

    for (int r = 0; r < ROWS; r++) {
        float4 nxt = make_float4(0.f, 0.f, 0.f, 0.f);
        if (i < 16) {
            int rr = (r + 2 < ROWS) ? (r + 2) : r;
            nxt = xg[rr * 16 + i];
        }

        const ulonglong2* hv = (const ulonglong2*)xs[r & 1];
        unsigned long long a0 = 0ull, a1 = 0ull, a2 = 0ull, a3 = 0ull;
#pragma unroll
        for (int k = 0; k < 16; k += 2) {
            ulonglong2 hA = hv[k];
            ulonglong2 hB = hv[k + 1];
            a0 = ffma2(w[2 * k],     hA.x, a0);
            a1 = ffma2(w[2 * k + 1], hA.y, a1);
            a2 = ffma2(w[2 * k + 2], hB.x, a2);
            a3 = ffma2(w[2 * k + 3], hB.y, a3);
        }
        unsigned long long s = fadd2(fadd2(a0, a1), fadd2(a2, a3));
        float2 f = unpack2(s);
        out[(row0 + r) * HH + i] = f.x + f.y + bias;

        if (i < 16) ((float4*)xs[(r + 1) & 1])[i] = pre;
        __syncthreads();
        pre = nxt;
    }
}

// ============================================================================
// Phase 2: sequential scan. ONE batch per block, 256 threads.
// j-split x2: thread pair (lane 2m, 2m+1) computes output i = tid>>1;
// even lane handles j in [0,64), odd lane j in [64,128). Partial dots are
// combined with shfl_xor(1) (intra-warp by construction).
//
// h state double-buffered in smem with the hi half PADDED to +272B so the
// even-lane and odd-lane broadcast reads hit disjoint banks (conflict-free
// single-phase LDS.128 wavefronts).
//
// 2 warps per SMSP -> cross-warp latency hiding; per-thread FMA chain halved.
// ============================================================================
#define HPAD 68   // hi half starts at float index 68 (byte 272, 16B-aligned)

__global__ __launch_bounds__(256, 1) void rnn_scan_kernel(
    const float* __restrict__ h0,
    const float* __restrict__ U,
    float* __restrict__ out)
{
    const int tid  = threadIdx.x;
    const int i    = tid >> 1;     // output index 0..127
    const int half = tid & 1;      // j-half
    const int b    = blockIdx.x;

    __shared__ __align__(16) float h_s[2][136];  // [buf][padded h]

    // U row i, this thread's 64 columns -> 32 packed regs
    unsigned long long u[32];
    const ulonglong2* Urow = (const ulonglong2*)(U + i * HH + half * 64);
#pragma unroll
    for (int k = 0; k < 16; k++) {
        ulonglong2 t = Urow[k];
        u[2 * k]     = t.x;
        u[2 * k + 1] = t.y;
    }

    const int sidx = (i < 64) ? i : (i + (HPAD - 64));  // padded store index
    if (half == 0) h_s[0][sidx] = h0[b * HH + i];

    float* op = out + (size_t)b * TT * HH + i;

    // prefetch distance 2 on xw (phase-1 data, consumed in-place)
    float xw0 = 0.f, xw1 = 0.f;
    if (half == 0) { xw0 = op[0]; xw1 = op[HH]; }
    __syncthreads();

    int buf = 0;
    float v = 0.f;
#pragma unroll 1
    for (int t = 0; t < TT; t++) {
        float xw2 = 0.f;
        if (half == 0) {
            int tp = (t + 2 < TT) ? (t + 2) : t;
            xw2 = op[tp * HH];
        }

        // partial dot over this thread's 64 j's (broadcast LDS, conflict-free)
        const ulonglong2* hv = (const ulonglong2*)(h_s[buf] + half * HPAD);
        unsigned long long a0 = 0ull, a1 = 0ull, a2 = 0ull, a3 = 0ull;
#pragma unroll
        for (int k = 0; k < 16; k += 2) {
            ulonglong2 hA = hv[k];
            ulonglong2 hB = hv[k + 1];
            a0 = ffma2(u[2 * k],     hA.x, a0);
            a1 = ffma2(u[2 * k + 1], hA.y, a1);
            a2 = ffma2(u[2 * k + 2], hB.x, a2);
            a3 = ffma2(u[2 * k + 3], hB.y, a3);
        }
        unsigned long long s = fadd2(fadd2(a0, a1), fadd2(a2, a3));
        float2 f = unpack2(s);
        float part = f.x + f.y;

        // combine the two halves (pair is intra-warp)
        part += __shfl_xor_sync(0xffffffffu, part, 1);

        if (half == 0) {
            v = tanh_fast(xw0 + part);
            op[t * HH]        = v;   // h_t output (overwrites xw[t])
            h_s[buf ^ 1][sidx] = v;  // publish new state
        }
        __syncthreads();

        xw0 = xw1;
        xw1 = xw2;
        buf ^= 1;
    }

    if (half == 0) out[(size_t)BB * TT * HH + b * HH + i] = v;
}

// ============================================================================
// Launch
// ============================================================================
extern "C" void kernel_launch(void* const* d_in, const int* in_sizes, int n_in,
                              void* d_out, int out_size)
{
    (void)in_sizes; (void)n_in; (void)out_size;
    const float* x    = (const float*)d_in[0];
    const float* h0   = (const float*)d_in[1];
    const float* W    = (const float*)d_in[2];
    const float* U    = (const float*)d_in[3];
    const float* b_ih = (const float*)d_in[4];
    const float* b_hh = (const float*)d_in[5];
    float* out = (float*)d_out;

    xw_gemm_kernel<<<(BB * TT) / 64, 128>>>(x, W, b_ih, b_hh, out);
    rnn_scan_kernel<<<BB, 256>>>(h0, U, out);
}

// round 6
// speedup vs baseline: 1.2947x; 1.1563x over previous
#include <cuda_runtime.h>
#include <cstdint>
#include <math.h>

// Problem constants
#define BB 64
#define TT 2048
#define II 64
#define HH 128

// ---------- packed f32x2 / fast-math helpers ----------
__device__ __forceinline__ unsigned long long ffma2(unsigned long long a,
                                                    unsigned long long b,
                                                    unsigned long long c) {
    unsigned long long d;
    asm("fma.rn.f32x2 %0, %1, %2, %3;" : "=l"(d) : "l"(a), "l"(b), "l"(c));
    return d;
}
__device__ __forceinline__ unsigned long long fadd2(unsigned long long a,
                                                    unsigned long long b) {
    unsigned long long d;
    asm("add.rn.f32x2 %0, %1, %2;" : "=l"(d) : "l"(a), "l"(b));
    return d;
}
__device__ __forceinline__ float2 unpack2(unsigned long long v) {
    float2 f;
    asm("mov.b64 {%0, %1}, %2;" : "=f"(f.x), "=f"(f.y) : "l"(v));
    return f;
}
__device__ __forceinline__ float tanh_fast(float x) {
    float y;
    asm("tanh.approx.f32 %0, %1;" : "=f"(y) : "f"(x));
    return y;
}

// ============================================================================
// Phase 1: xw[b,t,i] = dot(x[b,t,:], W[i,:]) + b_ih[i] + b_hh[i]
// Written into the output region of d_out (overwritten in-place by phase 2).
// One block = 64 (b,t) rows, 128 threads.
//
// 4 smem buffers in ping-pong PAIRS (race-free): interval with parity q reads
// xs[2q]=row r, xs[2q+1]=row r+1 and writes rows r+2, r+3 into the OPPOSITE
// pair xs[2q^2] (last read a full barrier interval ago). One sync / 2 rows.
// ============================================================================
__global__ __launch_bounds__(128) void xw_gemm_kernel(
    const float* __restrict__ x,
    const float* __restrict__ W,
    const float* __restrict__ b_ih,
    const float* __restrict__ b_hh,
    float* __restrict__ out)
{
    const int ROWS = 64;
    const int i = threadIdx.x;
    const long long row0 = (long long)blockIdx.x * ROWS;

    unsigned long long w[32];
    const ulonglong2* Wrow = (const ulonglong2*)(W + i * II);
#pragma unroll
    for (int k = 0; k < 16; k++) {
        ulonglong2 t = Wrow[k];
        w[2 * k]     = t.x;
        w[2 * k + 1] = t.y;
    }
    const float bias = b_ih[i] + b_hh[i];

    __shared__ __align__(16) float xs[4][II];

    const float4* xg = (const float4*)(x + row0 * II);

    float4 pre0 = make_float4(0.f, 0.f, 0.f, 0.f);
    float4 pre1 = pre0;
    if (i < 16) {
        ((float4*)xs[0])[i] = xg[i];        // row 0
        ((float4*)xs[1])[i] = xg[16 + i];   // row 1
        pre0 = xg[32 + i];                  // row 2
        pre1 = xg[48 + i];                  // row 3
    }
    __syncthreads();

#pragma unroll 1
    for (int r = 0; r < ROWS; r += 2) {
        const int base = ((r >> 1) & 1) * 2;   // pair holding rows r, r+1

        // prefetch rows r+4, r+5 (clamped; tail values never consumed)
        float4 nxt0 = make_float4(0.f, 0.f, 0.f, 0.f);
        float4 nxt1 = nxt0;
        if (i < 16) {
            int ra = (r + 4 < ROWS) ? (r + 4) : 0;
            int rb = (r + 5 < ROWS) ? (r + 5) : 0;
            nxt0 = xg[ra * 16 + i];
            nxt1 = xg[rb * 16 + i];
            // publish rows r+2, r+3 into the OPPOSITE pair (not read this interval)
            ((float4*)xs[base ^ 2])[i]       = pre0;
            ((float4*)xs[(base ^ 2) + 1])[i] = pre1;
        }

#pragma unroll
        for (int s = 0; s < 2; s++) {
            const ulonglong2* hv = (const ulonglong2*)xs[base + s];
            unsigned long long a0 = 0ull, a1 = 0ull, a2 = 0ull, a3 = 0ull;
#pragma unroll
            for (int k = 0; k < 16; k += 2) {
                ulonglong2 hA = hv[k];
                ulonglong2 hB = hv[k + 1];
                a0 = ffma2(w[2 * k],     hA.x, a0);
                a1 = ffma2(w[2 * k + 1], hA.y, a1);
                a2 = ffma2(w[2 * k + 2], hB.x, a2);
                a3 = ffma2(w[2 * k + 3], hB.y, a3);
            }
            unsigned long long sm = fadd2(fadd2(a0, a1), fadd2(a2, a3));
            float2 f = unpack2(sm);
            out[(row0 + r + s) * HH + i] = f.x + f.y + bias;
        }

        __syncthreads();
        pre0 = nxt0;   // rows r+6 wait in regs as (r+2)+4 next interval? no:
        pre1 = nxt1;   // invariant: pre = rows (r+2)+2, (r+2)+3  ✓ (r+4, r+5)
    }
}

// ============================================================================
// Phase 2: sequential scan. ONE batch per block, 256 threads, j-split x2.
// Thread pair (2m, 2m+1) computes output i = tid>>1; even lane j in [0,64),
// odd lane j in [64,128); halves combined with shfl_xor(1).
//
// Time loop unrolled x4 with 4 rotating xw prefetch registers: all 4 LDGs
// for steps t+4..t+7 issue at the body top (MLP=4); the rotating MOVs are a
// full body (~4 steps) downstream -> global-load latency off the critical
// path. h double-buffered: read h_s[s&1], write h_s[(s+1)&1] (race-free).
// ============================================================================
#define HPAD 68   // hi half starts at float index 68 (byte 272): disjoint banks

__global__ __launch_bounds__(256, 1) void rnn_scan_kernel(
    const float* __restrict__ h0,
    const float* __restrict__ U,
    float* __restrict__ out)
{
    const int tid  = threadIdx.x;
    const int i    = tid >> 1;     // output index 0..127
    const int half = tid & 1;      // j-half
    const int b    = blockIdx.x;

    __shared__ __align__(16) float h_s[2][136];  // [buf][padded h]

    // U row i, this thread's 64 columns -> 32 packed regs
    unsigned long long u[32];
    const ulonglong2* Urow = (const ulonglong2*)(U + i * HH + half * 64);
#pragma unroll
    for (int k = 0; k < 16; k++) {
        ulonglong2 t = Urow[k];
        u[2 * k]     = t.x;
        u[2 * k + 1] = t.y;
    }

    const int sidx = (i < 64) ? i : (i + (HPAD - 64));  // padded store index
    if (half == 0) h_s[0][sidx] = h0[b * HH + i];

    float* op = out + (size_t)b * TT * HH + i;

    // prefetch pipeline: xw[s] holds the input for step t+s
    float xw[4] = {0.f, 0.f, 0.f, 0.f};
    if (half == 0) {
        xw[0] = op[0];
        xw[1] = op[HH];
        xw[2] = op[2 * HH];
        xw[3] = op[3 * HH];
    }
    __syncthreads();

    float v = 0.f;
#pragma unroll 1
    for (int t = 0; t < TT; t += 4) {
        // issue next 4 prefetches up front (consumed 4+ steps later)
        float nxw[4];
        if (half == 0) {
#pragma unroll
            for (int s = 0; s < 4; s++) {
                int tp = t + 4 + s;
                tp = (tp < TT) ? tp : (TT - 1);   // tail values never consumed
                nxw[s] = op[(size_t)tp * HH];
            }
        }

#pragma unroll
        for (int s = 0; s < 4; s++) {
            // h_{t+s} lives in buffer s&1 (4 even -> parity consistent across iters)
            const ulonglong2* hv = (const ulonglong2*)(h_s[s & 1] + half * HPAD);
            unsigned long long a0 = 0ull, a1 = 0ull, a2 = 0ull, a3 = 0ull;
#pragma unroll
            for (int k = 0; k < 16; k += 2) {
                ulonglong2 hA = hv[k];
                ulonglong2 hB = hv[k + 1];
                a0 = ffma2(u[2 * k],     hA.x, a0);
                a1 = ffma2(u[2 * k + 1], hA.y, a1);
                a2 = ffma2(u[2 * k + 2], hB.x, a2);
                a3 = ffma2(u[2 * k + 3], hB.y, a3);
            }
            unsigned long long sm = fadd2(fadd2(a0, a1), fadd2(a2, a3));
            float2 f = unpack2(sm);
            float part = f.x + f.y;

            part += __shfl_xor_sync(0xffffffffu, part, 1);

            if (half == 0) {
                v = tanh_fast(xw[s] + part);
                op[(size_t)(t + s) * HH] = v;      // h_t output (overwrites xw[t])
                h_s[(s + 1) & 1][sidx]  = v;       // publish new state (other buf)
            }
            __syncthreads();
        }

        // rotation: these MOVs depend on LDGs issued a full body (~4 steps) ago
        if (half == 0) {
            xw[0] = nxw[0];
            xw[1] = nxw[1];
            xw[2] = nxw[2];
            xw[3] = nxw[3];
        }
    }

    if (half == 0) out[(size_t)BB * TT * HH + b * HH + i] = v;
}

// ============================================================================
// Launch
// ============================================================================
extern "C" void kernel_launch(void* const* d_in, const int* in_sizes, int n_in,
                              void* d_out, int out_size)
{
    (void)in_sizes; (void)n_in; (void)out_size;
    const float* x    = (const float*)d_in[0];
    const float* h0   = (const float*)d_in[1];
    const float* W    = (const float*)d_in[2];
    const float* U    = (const float*)d_in[3];
    const float* b_ih = (const float*)d_in[4];
    const float* b_hh = (const float*)d_in[5];
    float* out = (float*)d_out;

    xw_gemm_kernel<<<(BB * TT) / 64, 128>>>(x, W, b_ih, b_hh, out);
    rnn_scan_kernel<<<BB, 256>>>(h0, U, out);
}